// round 3
// baseline (speedup 1.0000x reference)
#include <cuda_runtime.h>

#define BATCH 16
#define HH 512
#define WW 512
#define TR 32                // rows per block in accumulation kernel

// ---- scratch (no allocations allowed) ----
__device__ float g_colsum[BATCH][WW];   // de_h summed over H, per column (only [0..510] used)
__device__ float g_rowsum[BATCH][HH];   // de_v summed over W, per row    (only [0..510] used)
__device__ int   g_dec[BATCH][4];       // kh, blocked_h, kv, blocked_v

// -------------------------------------------------------------------------
// Kernel 0: zero the per-line accumulators (graph replays must be clean)
// -------------------------------------------------------------------------
__global__ void jb_zero_kernel() {
    int i = blockIdx.x * blockDim.x + threadIdx.x;
    if (i < BATCH * WW) {
        (&g_colsum[0][0])[i] = 0.0f;
        (&g_rowsum[0][0])[i] = 0.0f;
    }
}

// -------------------------------------------------------------------------
// Kernel 1: streaming luminance + clipped cross-diffs + line reductions
// grid = (H/TR, BATCH), block = 512 threads (one column each)
// -------------------------------------------------------------------------
__global__ __launch_bounds__(512) void jb_accum_kernel(
    const float* __restrict__ ref, const float* __restrict__ tgt)
{
    const int b  = blockIdx.y;
    const int r0 = blockIdx.x * TR;
    const int w  = threadIdx.x;

    __shared__ float s_lr[2][WW];
    __shared__ float s_lt[2][WW];

    const float* rB = ref + (size_t)b * 3 * HH * WW;
    const float* tB = tgt + (size_t)b * 3 * HH * WW;

    float col_acc = 0.0f;
    float prev_lr = 0.0f, prev_lt = 0.0f;

    // rows r0 .. r0+TR-1 owned by this block, plus one extra row for the
    // vertical pair at the tile boundary (unless at the bottom of the image).
    const int rend = min(r0 + TR + 1, HH);

    for (int r = r0; r < rend; ++r) {
        const int buf = r & 1;
        const float* rp = rB + (size_t)r * WW + w;
        const float* tp = tB + (size_t)r * WW + w;
        // luminance (channel stride = H*W)
        float lr = 0.299f * rp[0] + 0.587f * rp[HH * WW] + 0.114f * rp[2 * HH * WW];
        float lt = 0.299f * tp[0] + 0.587f * tp[HH * WW] + 0.114f * tp[2 * HH * WW];
        s_lr[buf][w] = lr;
        s_lt[buf][w] = lt;
        __syncthreads();   // double buffer: one barrier per row is sufficient

        // horizontal excess energy -> column sums (rows r0..r0+TR-1 only)
        if (r < r0 + TR && w < WW - 1) {
            float eh_r = fabsf(lr - s_lr[buf][w + 1]);
            float eh_t = fabsf(lt - s_lt[buf][w + 1]);
            col_acc += fmaxf(eh_t - eh_r, 0.0f);
        }

        // vertical excess energy for row (r-1) -> row sum (exclusive to block)
        if (r > r0) {
            float dv = fmaxf(fabsf(prev_lt - lt) - fabsf(prev_lr - lr), 0.0f);
            #pragma unroll
            for (int off = 16; off > 0; off >>= 1)
                dv += __shfl_down_sync(0xffffffffu, dv, off);
            if ((w & 31) == 0)
                atomicAdd(&g_rowsum[b][r - 1], dv);
        }
        prev_lr = lr;
        prev_lt = lt;
    }
    atomicAdd(&g_colsum[b][w], col_acc);
}

// -------------------------------------------------------------------------
// Kernel 2: per-batch phase decision (one block per batch, 128 threads:
// threads 0..63 handle columns (h), 64..127 handle rows (v))
// -------------------------------------------------------------------------
__global__ void jb_decide_kernel() {
    const int b = blockIdx.x;
    const int t = threadIdx.x;

    __shared__ float ph[2][8];
    if (t < 16) ph[t >> 3][t & 7] = 0.0f;
    __syncthreads();

    const int grp = t >> 6;        // 0 = h (cols), 1 = v (rows)
    const int i0  = t & 63;
    const float* src = grp ? g_rowsum[b] : g_colsum[b];

    // indices i0, i0+64, ... share phase i0%8; convert sums to line means
    float acc = 0.0f;
    for (int i = i0; i < 511; i += 64)
        acc += src[i] * (1.0f / 512.0f);
    atomicAdd(&ph[grp][i0 & 7], acc);
    __syncthreads();

    if (t < 2) {
        float total = 0.0f;
        #pragma unroll
        for (int k = 0; k < 8; ++k) total += ph[t][k];
        float best_r = -1.0f;
        int   best_k = 0;
        #pragma unroll
        for (int k = 0; k < 8; ++k) {
            float cnt   = (k < 7) ? 64.0f : 63.0f;   // 511 lines: phases 0..6 have 64
            float a_k   = ph[t][k] / cnt;
            float bg    = (total - ph[t][k]) / (511.0f - cnt);
            float ratio = a_k / (bg + 1e-8f);
            if (ratio > best_r) { best_r = ratio; best_k = k; }  // first-max, like jnp.argmax
        }
        int blocked = best_r > (1.0f / 0.35f);
        g_dec[b][t * 2 + 0] = best_k;
        g_dec[b][t * 2 + 1] = blocked;
    }
}

// -------------------------------------------------------------------------
// Kernel 3: paint the output mask, float4 stores
// one thread per 4 pixels: B*H*W/4 = 1,048,576 threads
// -------------------------------------------------------------------------
__global__ __launch_bounds__(256) void jb_write_kernel(float* __restrict__ out) {
    const int idx = blockIdx.x * blockDim.x + threadIdx.x;
    const int w4 = (idx & (WW / 4 - 1)) * 4;     // W/4 = 128 -> low 7 bits
    const int r  = (idx >> 7) & (HH - 1);
    const int b  = idx >> 16;                     // 7 + 9 bits per image

    const int kh = g_dec[b][0], bh = g_dec[b][1];
    const int kv = g_dec[b][2], bv = g_dec[b][3];

    const float vrow = (bv && ((r & 7) == kv) && (r < HH - 1)) ? 1.0f : 0.0f;

    float4 o;
    float* op = reinterpret_cast<float*>(&o);
    #pragma unroll
    for (int j = 0; j < 4; ++j) {
        int w = w4 + j;
        float vcol = (bh && ((w & 7) == kh) && (w < WW - 1)) ? 1.0f : 0.0f;
        op[j] = (vrow + vcol > 0.0f) ? 1.0f : 0.0f;
    }
    reinterpret_cast<float4*>(out)[idx] = o;
}

// -------------------------------------------------------------------------
extern "C" void kernel_launch(void* const* d_in, const int* in_sizes, int n_in,
                              void* d_out, int out_size)
{
    const float* ref = (const float*)d_in[0];
    const float* tgt = (const float*)d_in[1];
    float* out = (float*)d_out;

    jb_zero_kernel<<<(BATCH * WW + 255) / 256, 256>>>();

    dim3 agrid(HH / TR, BATCH);
    jb_accum_kernel<<<agrid, 512>>>(ref, tgt);

    jb_decide_kernel<<<BATCH, 128>>>();

    int npix4 = BATCH * HH * WW / 4;
    jb_write_kernel<<<npix4 / 256, 256>>>(out);
}

// round 4
// speedup vs baseline: 1.1008x; 1.1008x over previous
#include <cuda_runtime.h>

#define BATCH 16
#define HH 512
#define WW 512
#define HWSZ (HH * WW)
#define TR 16                 // rows per warp-tile in accumulation kernel

// ---- scratch (no allocations allowed; zero-initialized at module load) ----
__device__ float g_colsum[BATCH][WW];   // de_h summed over H, per column (only [0..510] used)
__device__ float g_rowsum[BATCH][HH];   // de_v summed over W, per row    (only [0..510] used)
__device__ int   g_dec[BATCH][4];       // kh, blocked_h, kv, blocked_v

__device__ __forceinline__ float lum1(const float* p) {
    return 0.299f * p[0] + 0.587f * p[HWSZ] + 0.114f * p[2 * HWSZ];
}
__device__ __forceinline__ float4 lum4(float4 c0, float4 c1, float4 c2) {
    float4 l;
    l.x = 0.299f * c0.x + 0.587f * c1.x + 0.114f * c2.x;
    l.y = 0.299f * c0.y + 0.587f * c1.y + 0.114f * c2.y;
    l.z = 0.299f * c0.z + 0.587f * c1.z + 0.114f * c2.z;
    l.w = 0.299f * c0.w + 0.587f * c1.w + 0.114f * c2.w;
    return l;
}
// clipped excess: max(|t0-t1| - |r0-r1|, 0)
__device__ __forceinline__ float dexc(float t0, float t1, float r0, float r1) {
    return fmaxf(fabsf(t0 - t1) - fabsf(r0 - r1), 0.0f);
}

// -------------------------------------------------------------------------
// Kernel 1: barrier-free streaming reduction.
// Each WARP owns a 128-col x TR-row strip. float4 per lane (4 cols).
// Horizontal neighbor via shuffle; lane 31 recomputes the boundary lum.
// Vertical carried in registers; warp-reduce + 1 atomic per row.
// grid: BATCH * (H/TR) * 4 strips warps, 8 warps (256 thr) per block.
// -------------------------------------------------------------------------
__global__ __launch_bounds__(256) void jb_accum_kernel(
    const float* __restrict__ ref, const float* __restrict__ tgt)
{
    const int gw    = blockIdx.x * 8 + (threadIdx.x >> 5);
    const int lane  = threadIdx.x & 31;
    const int b     = gw >> 7;            // 128 warps per batch (32 tiles * 4 strips)
    const int rem   = gw & 127;
    const int tile  = rem >> 2;
    const int strip = rem & 3;
    const int r0    = tile * TR;
    const int c0    = strip * 128 + lane * 4;

    const float* rB = ref + (size_t)b * 3 * HWSZ;
    const float* tB = tgt + (size_t)b * 3 * HWSZ;

    const bool bnd_load = (lane == 31) && (strip < 3);   // need col c0+4 from next strip
    const bool bnd_skip = (lane == 31) && (strip == 3);  // col 511 has no right neighbor

    float4 cacc = make_float4(0.f, 0.f, 0.f, 0.f);
    float4 plr, plt;
    const int rend = min(r0 + TR + 1, HH);

    for (int r = r0; r < rend; ++r) {
        const float* rp = rB + (size_t)r * WW + c0;
        const float* tp = tB + (size_t)r * WW + c0;
        float4 rc0 = *reinterpret_cast<const float4*>(rp);
        float4 rc1 = *reinterpret_cast<const float4*>(rp + HWSZ);
        float4 rc2 = *reinterpret_cast<const float4*>(rp + 2 * HWSZ);
        float4 tc0 = *reinterpret_cast<const float4*>(tp);
        float4 tc1 = *reinterpret_cast<const float4*>(tp + HWSZ);
        float4 tc2 = *reinterpret_cast<const float4*>(tp + 2 * HWSZ);
        float4 lr = lum4(rc0, rc1, rc2);
        float4 lt = lum4(tc0, tc1, tc2);

        // ---- horizontal (rows r0 .. r0+TR-1 only) ----
        if (r < r0 + TR) {
            float nr = __shfl_down_sync(0xffffffffu, lr.x, 1);
            float nt = __shfl_down_sync(0xffffffffu, lt.x, 1);
            if (bnd_load) {           // recompute boundary luminance (col c0+4)
                nr = lum1(rp + 4);
                nt = lum1(tp + 4);
            }
            cacc.x += dexc(lt.x, lt.y, lr.x, lr.y);
            cacc.y += dexc(lt.y, lt.z, lr.y, lr.z);
            cacc.z += dexc(lt.z, lt.w, lr.z, lr.w);
            if (!bnd_skip)
                cacc.w += dexc(lt.w, nt, lr.w, nr);
        }

        // ---- vertical pair (r-1, r) ----
        if (r > r0) {
            float dv = dexc(plt.x, lt.x, plr.x, lr.x)
                     + dexc(plt.y, lt.y, plr.y, lr.y)
                     + dexc(plt.z, lt.z, plr.z, lr.z)
                     + dexc(plt.w, lt.w, plr.w, lr.w);
            #pragma unroll
            for (int off = 16; off > 0; off >>= 1)
                dv += __shfl_down_sync(0xffffffffu, dv, off);
            if (lane == 0)
                atomicAdd(&g_rowsum[b][r - 1], dv);
        }
        plr = lr; plt = lt;
    }

    atomicAdd(&g_colsum[b][c0 + 0], cacc.x);
    atomicAdd(&g_colsum[b][c0 + 1], cacc.y);
    atomicAdd(&g_colsum[b][c0 + 2], cacc.z);
    atomicAdd(&g_colsum[b][c0 + 3], cacc.w);
}

// -------------------------------------------------------------------------
// Kernel 2: per-batch phase decision. Also ZEROES the accumulators it
// consumed, so graph replays start clean (no separate zero kernel).
// one block per batch, 128 threads: 0..63 cols (h), 64..127 rows (v).
// -------------------------------------------------------------------------
__global__ void jb_decide_kernel() {
    const int b = blockIdx.x;
    const int t = threadIdx.x;

    __shared__ float ph[2][8];
    if (t < 16) ph[t >> 3][t & 7] = 0.0f;
    __syncthreads();

    const int grp = t >> 6;        // 0 = h (cols), 1 = v (rows)
    const int i0  = t & 63;
    float* src = grp ? g_rowsum[b] : g_colsum[b];

    // indices i0, i0+64, ... share phase i0%8; convert sums to line means
    float acc = 0.0f;
    for (int i = i0; i < 511; i += 64) {
        acc += src[i] * (1.0f / 512.0f);
        src[i] = 0.0f;             // reset for next graph replay
    }
    atomicAdd(&ph[grp][i0 & 7], acc);
    __syncthreads();

    if (t < 2) {
        float total = 0.0f;
        #pragma unroll
        for (int k = 0; k < 8; ++k) total += ph[t][k];
        float best_r = -1.0f;
        int   best_k = 0;
        #pragma unroll
        for (int k = 0; k < 8; ++k) {
            float cnt   = (k < 7) ? 64.0f : 63.0f;   // 511 lines: phases 0..6 have 64
            float a_k   = ph[t][k] / cnt;
            float bg    = (total - ph[t][k]) / (511.0f - cnt);
            float ratio = a_k / (bg + 1e-8f);
            if (ratio > best_r) { best_r = ratio; best_k = k; }  // first-max, like argmax
        }
        int blocked = best_r > (1.0f / 0.35f);
        g_dec[b][t * 2 + 0] = best_k;
        g_dec[b][t * 2 + 1] = blocked;
    }
}

// -------------------------------------------------------------------------
// Kernel 3: paint the output mask. 16 floats (4 x STG.128) per thread.
// (w & 7) folds to the compile-time (j & 7) since chunks start on a
// 16-aligned column.
// -------------------------------------------------------------------------
__global__ __launch_bounds__(256) void jb_write_kernel(float* __restrict__ out) {
    const int idx = blockIdx.x * 256 + threadIdx.x;   // B*H*W/16 = 262144 threads
    const int c16 = idx & 31;            // 32 chunks of 16 cols per row
    const int r   = (idx >> 5) & (HH - 1);
    const int b   = idx >> 14;

    const int kh = g_dec[b][0], bh = g_dec[b][1];
    const int kv = g_dec[b][2], bv = g_dec[b][3];

    const bool vrow = bv && ((r & 7) == kv) && (r < HH - 1);
    const bool tail = (c16 == 31);       // chunk containing col 511

    float4 o[4];
    float* op = reinterpret_cast<float*>(o);
    #pragma unroll
    for (int j = 0; j < 16; ++j) {
        bool vcol = bh && ((j & 7) == kh) && !(tail && j == 15);
        op[j] = (vrow || vcol) ? 1.0f : 0.0f;
    }
    float4* dst = reinterpret_cast<float4*>(out + (size_t)idx * 16);
    dst[0] = o[0]; dst[1] = o[1]; dst[2] = o[2]; dst[3] = o[3];
}

// -------------------------------------------------------------------------
extern "C" void kernel_launch(void* const* d_in, const int* in_sizes, int n_in,
                              void* d_out, int out_size)
{
    const float* ref = (const float*)d_in[0];
    const float* tgt = (const float*)d_in[1];
    float* out = (float*)d_out;

    // 16 batches * 32 tiles * 4 strips = 2048 warps -> 256 blocks of 8 warps
    jb_accum_kernel<<<256, 256>>>(ref, tgt);

    jb_decide_kernel<<<BATCH, 128>>>();

    jb_write_kernel<<<BATCH * HH * WW / 16 / 256, 256>>>(out);
}

// round 5
// speedup vs baseline: 1.3700x; 1.2445x over previous
#include <cuda_runtime.h>

#define BATCH 16
#define HH 512
#define WW 512
#define HWSZ (HH * WW)
#define TR 8                  // rows per warp-tile in accumulation kernel

// ---- scratch (no allocations allowed; zero-initialized at module load) ----
__device__ float g_colsum[BATCH][WW];   // de_h summed over H, per column (only [0..510] used)
__device__ float g_rowsum[BATCH][HH];   // de_v summed over W, per row    (only [0..510] used)
__device__ int   g_dec[BATCH][4];       // kh, blocked_h, kv, blocked_v

__device__ __forceinline__ float lum1(const float* p) {
    return 0.299f * p[0] + 0.587f * p[HWSZ] + 0.114f * p[2 * HWSZ];
}
__device__ __forceinline__ float4 lum4(float4 c0, float4 c1, float4 c2) {
    float4 l;
    l.x = 0.299f * c0.x + 0.587f * c1.x + 0.114f * c2.x;
    l.y = 0.299f * c0.y + 0.587f * c1.y + 0.114f * c2.y;
    l.z = 0.299f * c0.z + 0.587f * c1.z + 0.114f * c2.z;
    l.w = 0.299f * c0.w + 0.587f * c1.w + 0.114f * c2.w;
    return l;
}
// clipped excess: max(|t0-t1| - |r0-r1|, 0)
__device__ __forceinline__ float dexc(float t0, float t1, float r0, float r1) {
    return fmaxf(fabsf(t0 - t1) - fabsf(r0 - r1), 0.0f);
}

// -------------------------------------------------------------------------
// Kernel 1: barrier-free streaming reduction.
// Each WARP owns a 128-col x TR-row strip. float4 per lane (4 cols).
// Horizontal neighbor via shuffle; lane 31 recomputes the boundary lum.
// Vertical carried in registers; warp-reduce + 1 atomic per row.
// Fixed TR+1 trip count; phantom row (r0+TR==512 for the last tile) is
// clamped to row 511 -> its vertical dexc is identically 0 and its rowsum
// target (index 511) is never read, so no divergence and no error.
// grid: BATCH * (H/TR) * 4 strip-warps = 4096 warps, 8 warps/block.
// -------------------------------------------------------------------------
__global__ __launch_bounds__(256) void jb_accum_kernel(
    const float* __restrict__ ref, const float* __restrict__ tgt)
{
    const int gw    = blockIdx.x * 8 + (threadIdx.x >> 5);
    const int lane  = threadIdx.x & 31;
    const int b     = gw >> 8;            // 256 warps per batch (64 tiles * 4 strips)
    const int rem   = gw & 255;
    const int tile  = rem >> 2;
    const int strip = rem & 3;
    const int r0    = tile * TR;
    const int c0    = strip * 128 + lane * 4;

    const float* rB = ref + (size_t)b * 3 * HWSZ;
    const float* tB = tgt + (size_t)b * 3 * HWSZ;

    const bool bnd_load = (lane == 31) && (strip < 3);   // need col c0+4 from next strip
    const bool bnd_skip = (lane == 31) && (strip == 3);  // col 511 has no right neighbor

    float4 cacc = make_float4(0.f, 0.f, 0.f, 0.f);
    float4 plr, plt;

    #pragma unroll 3
    for (int i = 0; i <= TR; ++i) {
        const int r = min(r0 + i, HH - 1);       // clamp phantom row
        const float* rp = rB + (size_t)r * WW + c0;
        const float* tp = tB + (size_t)r * WW + c0;
        float4 rc0 = *reinterpret_cast<const float4*>(rp);
        float4 rc1 = *reinterpret_cast<const float4*>(rp + HWSZ);
        float4 rc2 = *reinterpret_cast<const float4*>(rp + 2 * HWSZ);
        float4 tc0 = *reinterpret_cast<const float4*>(tp);
        float4 tc1 = *reinterpret_cast<const float4*>(tp + HWSZ);
        float4 tc2 = *reinterpret_cast<const float4*>(tp + 2 * HWSZ);
        float4 lr = lum4(rc0, rc1, rc2);
        float4 lt = lum4(tc0, tc1, tc2);

        // ---- horizontal (first TR iterations only) ----
        if (i < TR) {
            float nr = __shfl_down_sync(0xffffffffu, lr.x, 1);
            float nt = __shfl_down_sync(0xffffffffu, lt.x, 1);
            if (bnd_load) {           // recompute boundary luminance (col c0+4)
                nr = lum1(rp + 4);
                nt = lum1(tp + 4);
            }
            cacc.x += dexc(lt.x, lt.y, lr.x, lr.y);
            cacc.y += dexc(lt.y, lt.z, lr.y, lr.z);
            cacc.z += dexc(lt.z, lt.w, lr.z, lr.w);
            if (!bnd_skip)
                cacc.w += dexc(lt.w, nt, lr.w, nr);
        }

        // ---- vertical pair (r-1, r) ----
        if (i > 0) {
            float dv = dexc(plt.x, lt.x, plr.x, lr.x)
                     + dexc(plt.y, lt.y, plr.y, lr.y)
                     + dexc(plt.z, lt.z, plr.z, lr.z)
                     + dexc(plt.w, lt.w, plr.w, lr.w);
            #pragma unroll
            for (int off = 16; off > 0; off >>= 1)
                dv += __shfl_down_sync(0xffffffffu, dv, off);
            if (lane == 0)
                atomicAdd(&g_rowsum[b][r0 + i - 1], dv);   // phantom writes idx 511 (unused)
        }
        plr = lr; plt = lt;
    }

    atomicAdd(&g_colsum[b][c0 + 0], cacc.x);
    atomicAdd(&g_colsum[b][c0 + 1], cacc.y);
    atomicAdd(&g_colsum[b][c0 + 2], cacc.z);
    atomicAdd(&g_colsum[b][c0 + 3], cacc.w);
}

// -------------------------------------------------------------------------
// Kernel 2: per-batch phase decision. Also ZEROES the accumulators it
// consumed, so graph replays start clean (no separate zero kernel).
// one block per batch, 128 threads: 0..63 cols (h), 64..127 rows (v).
// -------------------------------------------------------------------------
__global__ void jb_decide_kernel() {
    const int b = blockIdx.x;
    const int t = threadIdx.x;

    __shared__ float ph[2][8];
    if (t < 16) ph[t >> 3][t & 7] = 0.0f;
    __syncthreads();

    const int grp = t >> 6;        // 0 = h (cols), 1 = v (rows)
    const int i0  = t & 63;
    float* src = grp ? g_rowsum[b] : g_colsum[b];

    // indices i0, i0+64, ... share phase i0%8; convert sums to line means
    float acc = 0.0f;
    for (int i = i0; i < 512; i += 64) {
        if (i < 511) acc += src[i] * (1.0f / 512.0f);
        src[i] = 0.0f;             // reset (incl. idx 511) for next graph replay
    }
    atomicAdd(&ph[grp][i0 & 7], acc);
    __syncthreads();

    if (t < 2) {
        float total = 0.0f;
        #pragma unroll
        for (int k = 0; k < 8; ++k) total += ph[t][k];
        float best_r = -1.0f;
        int   best_k = 0;
        #pragma unroll
        for (int k = 0; k < 8; ++k) {
            float cnt   = (k < 7) ? 64.0f : 63.0f;   // 511 lines: phases 0..6 have 64
            float a_k   = ph[t][k] / cnt;
            float bg    = (total - ph[t][k]) / (511.0f - cnt);
            float ratio = a_k / (bg + 1e-8f);
            if (ratio > best_r) { best_r = ratio; best_k = k; }  // first-max, like argmax
        }
        int blocked = best_r > (1.0f / 0.35f);
        g_dec[b][t * 2 + 0] = best_k;
        g_dec[b][t * 2 + 1] = blocked;
    }
}

// -------------------------------------------------------------------------
// Kernel 3: paint the output mask. 16 floats (4 x STG.128) per thread.
// -------------------------------------------------------------------------
__global__ __launch_bounds__(256) void jb_write_kernel(float* __restrict__ out) {
    const int idx = blockIdx.x * 256 + threadIdx.x;   // B*H*W/16 = 262144 threads
    const int c16 = idx & 31;            // 32 chunks of 16 cols per row
    const int r   = (idx >> 5) & (HH - 1);
    const int b   = idx >> 14;

    const int kh = g_dec[b][0], bh = g_dec[b][1];
    const int kv = g_dec[b][2], bv = g_dec[b][3];

    const bool vrow = bv && ((r & 7) == kv) && (r < HH - 1);
    const bool tail = (c16 == 31);       // chunk containing col 511

    float4 o[4];
    float* op = reinterpret_cast<float*>(o);
    #pragma unroll
    for (int j = 0; j < 16; ++j) {
        bool vcol = bh && ((j & 7) == kh) && !(tail && j == 15);
        op[j] = (vrow || vcol) ? 1.0f : 0.0f;
    }
    float4* dst = reinterpret_cast<float4*>(out + (size_t)idx * 16);
    dst[0] = o[0]; dst[1] = o[1]; dst[2] = o[2]; dst[3] = o[3];
}

// -------------------------------------------------------------------------
extern "C" void kernel_launch(void* const* d_in, const int* in_sizes, int n_in,
                              void* d_out, int out_size)
{
    const float* ref = (const float*)d_in[0];
    const float* tgt = (const float*)d_in[1];
    float* out = (float*)d_out;

    // 16 batches * 64 tiles * 4 strips = 4096 warps -> 512 blocks of 8 warps
    jb_accum_kernel<<<512, 256>>>(ref, tgt);

    jb_decide_kernel<<<BATCH, 128>>>();

    jb_write_kernel<<<BATCH * HH * WW / 16 / 256, 256>>>(out);
}

// round 6
// speedup vs baseline: 1.5203x; 1.1098x over previous
#include <cuda_runtime.h>

#define BATCH 16
#define HH 512
#define WW 512
#define HWSZ (HH * WW)
#define TR 8                  // rows per warp-tile in accumulation kernel

// ---- scratch (no allocations allowed; zero-initialized at module load) ----
__device__ float g_colsum[BATCH][WW];   // de_h summed over H, per column (only [0..510] used)
__device__ float g_rowsum[BATCH][HH];   // de_v summed over W, per row    (only [0..510] used)
__device__ int   g_dec[BATCH][4];       // kh, blocked_h, kv, blocked_v

__device__ __forceinline__ float lum1(const float* p) {
    return 0.299f * p[0] + 0.587f * p[HWSZ] + 0.114f * p[2 * HWSZ];
}
__device__ __forceinline__ float2 lum2(float2 c0, float2 c1, float2 c2) {
    float2 l;
    l.x = 0.299f * c0.x + 0.587f * c1.x + 0.114f * c2.x;
    l.y = 0.299f * c0.y + 0.587f * c1.y + 0.114f * c2.y;
    return l;
}
// clipped excess: max(|t0-t1| - |r0-r1|, 0)
__device__ __forceinline__ float dexc(float t0, float t1, float r0, float r1) {
    return fmaxf(fabsf(t0 - t1) - fabsf(r0 - r1), 0.0f);
}

// -------------------------------------------------------------------------
// Kernel 1: barrier-free streaming reduction, float2 per lane (2 cols).
// Each WARP owns a 64-col x TR-row strip -> 8 strips across the width.
// Horizontal neighbor via shuffle; lane 31 recomputes the boundary lum.
// Vertical carried in registers; warp-reduce + 1 atomic per row.
// Fixed TR+1 trip count; phantom row (r0+TR==512 for the last tile) is
// clamped to row 511 -> vertical dexc is identically 0, rowsum idx 511
// is never read.
// grid: BATCH * (H/TR) * 8 strip-warps = 8192 warps, 8 warps/block.
// -------------------------------------------------------------------------
__global__ __launch_bounds__(256) void jb_accum_kernel(
    const float* __restrict__ ref, const float* __restrict__ tgt)
{
    const int gw    = blockIdx.x * 8 + (threadIdx.x >> 5);
    const int lane  = threadIdx.x & 31;
    const int b     = gw >> 9;            // 512 warps per batch (64 tiles * 8 strips)
    const int rem   = gw & 511;
    const int tile  = rem >> 3;
    const int strip = rem & 7;
    const int r0    = tile * TR;
    const int c0    = strip * 64 + lane * 2;

    const float* rB = ref + (size_t)b * 3 * HWSZ;
    const float* tB = tgt + (size_t)b * 3 * HWSZ;

    const bool bnd_load = (lane == 31) && (strip < 7);   // need col c0+2 from next strip
    const bool bnd_skip = (lane == 31) && (strip == 7);  // col 511 has no right neighbor

    float2 cacc = make_float2(0.f, 0.f);
    float2 plr, plt;

    #pragma unroll 3
    for (int i = 0; i <= TR; ++i) {
        const int r = min(r0 + i, HH - 1);       // clamp phantom row
        const float* rp = rB + (size_t)r * WW + c0;
        const float* tp = tB + (size_t)r * WW + c0;
        float2 rc0 = *reinterpret_cast<const float2*>(rp);
        float2 rc1 = *reinterpret_cast<const float2*>(rp + HWSZ);
        float2 rc2 = *reinterpret_cast<const float2*>(rp + 2 * HWSZ);
        float2 tc0 = *reinterpret_cast<const float2*>(tp);
        float2 tc1 = *reinterpret_cast<const float2*>(tp + HWSZ);
        float2 tc2 = *reinterpret_cast<const float2*>(tp + 2 * HWSZ);
        float2 lr = lum2(rc0, rc1, rc2);
        float2 lt = lum2(tc0, tc1, tc2);

        // ---- horizontal (first TR iterations only) ----
        if (i < TR) {
            float nr = __shfl_down_sync(0xffffffffu, lr.x, 1);
            float nt = __shfl_down_sync(0xffffffffu, lt.x, 1);
            if (bnd_load) {           // recompute boundary luminance (col c0+2)
                nr = lum1(rp + 2);
                nt = lum1(tp + 2);
            }
            cacc.x += dexc(lt.x, lt.y, lr.x, lr.y);
            if (!bnd_skip)
                cacc.y += dexc(lt.y, nt, lr.y, nr);
        }

        // ---- vertical pair (r-1, r) ----
        if (i > 0) {
            float dv = dexc(plt.x, lt.x, plr.x, lr.x)
                     + dexc(plt.y, lt.y, plr.y, lr.y);
            #pragma unroll
            for (int off = 16; off > 0; off >>= 1)
                dv += __shfl_down_sync(0xffffffffu, dv, off);
            if (lane == 0)
                atomicAdd(&g_rowsum[b][r0 + i - 1], dv);   // phantom hits idx 511 (unused)
        }
        plr = lr; plt = lt;
    }

    atomicAdd(&g_colsum[b][c0 + 0], cacc.x);
    atomicAdd(&g_colsum[b][c0 + 1], cacc.y);
}

// -------------------------------------------------------------------------
// Kernel 2: per-batch phase decision. Also ZEROES the accumulators it
// consumed, so graph replays start clean (no separate zero kernel).
// one block per batch, 128 threads: 0..63 cols (h), 64..127 rows (v).
// -------------------------------------------------------------------------
__global__ void jb_decide_kernel() {
    const int b = blockIdx.x;
    const int t = threadIdx.x;

    __shared__ float ph[2][8];
    if (t < 16) ph[t >> 3][t & 7] = 0.0f;
    __syncthreads();

    const int grp = t >> 6;        // 0 = h (cols), 1 = v (rows)
    const int i0  = t & 63;
    float* src = grp ? g_rowsum[b] : g_colsum[b];

    // indices i0, i0+64, ... share phase i0%8; convert sums to line means
    float acc = 0.0f;
    for (int i = i0; i < 512; i += 64) {
        if (i < 511) acc += src[i] * (1.0f / 512.0f);
        src[i] = 0.0f;             // reset (incl. idx 511) for next graph replay
    }
    atomicAdd(&ph[grp][i0 & 7], acc);
    __syncthreads();

    if (t < 2) {
        float total = 0.0f;
        #pragma unroll
        for (int k = 0; k < 8; ++k) total += ph[t][k];
        float best_r = -1.0f;
        int   best_k = 0;
        #pragma unroll
        for (int k = 0; k < 8; ++k) {
            float cnt   = (k < 7) ? 64.0f : 63.0f;   // 511 lines: phases 0..6 have 64
            float a_k   = ph[t][k] / cnt;
            float bg    = (total - ph[t][k]) / (511.0f - cnt);
            float ratio = a_k / (bg + 1e-8f);
            if (ratio > best_r) { best_r = ratio; best_k = k; }  // first-max, like argmax
        }
        int blocked = best_r > (1.0f / 0.35f);
        g_dec[b][t * 2 + 0] = best_k;
        g_dec[b][t * 2 + 1] = blocked;
    }
}

// -------------------------------------------------------------------------
// Kernel 3: paint the output mask. 16 floats (4 x STG.128) per thread.
// -------------------------------------------------------------------------
__global__ __launch_bounds__(256) void jb_write_kernel(float* __restrict__ out) {
    const int idx = blockIdx.x * 256 + threadIdx.x;   // B*H*W/16 = 262144 threads
    const int c16 = idx & 31;            // 32 chunks of 16 cols per row
    const int r   = (idx >> 5) & (HH - 1);
    const int b   = idx >> 14;

    const int kh = g_dec[b][0], bh = g_dec[b][1];
    const int kv = g_dec[b][2], bv = g_dec[b][3];

    const bool vrow = bv && ((r & 7) == kv) && (r < HH - 1);
    const bool tail = (c16 == 31);       // chunk containing col 511

    float4 o[4];
    float* op = reinterpret_cast<float*>(o);
    #pragma unroll
    for (int j = 0; j < 16; ++j) {
        bool vcol = bh && ((j & 7) == kh) && !(tail && j == 15);
        op[j] = (vrow || vcol) ? 1.0f : 0.0f;
    }
    float4* dst = reinterpret_cast<float4*>(out + (size_t)idx * 16);
    dst[0] = o[0]; dst[1] = o[1]; dst[2] = o[2]; dst[3] = o[3];
}

// -------------------------------------------------------------------------
extern "C" void kernel_launch(void* const* d_in, const int* in_sizes, int n_in,
                              void* d_out, int out_size)
{
    const float* ref = (const float*)d_in[0];
    const float* tgt = (const float*)d_in[1];
    float* out = (float*)d_out;

    // 16 batches * 64 tiles * 8 strips = 8192 warps -> 1024 blocks of 8 warps
    jb_accum_kernel<<<1024, 256>>>(ref, tgt);

    jb_decide_kernel<<<BATCH, 128>>>();

    jb_write_kernel<<<BATCH * HH * WW / 16 / 256, 256>>>(out);
}